// round 8
// baseline (speedup 1.0000x reference)
#include <cuda_runtime.h>
#include <cstdint>

// Problem constants
#define NN 64
#define CC 256
#define GG 4
#define HS 16
#define WW 44
#define KK 16
#define NPOS 704              // HS*WW
#define NPOS4 176             // NPOS/4
#define TOPK 88               // int(704*0.125)
#define GATE 0.05f
#define EPSV 1e-6f
#define CH_STRIDE 2816        // GG*NPOS, channel stride in floats
#define TILE_STRIDE 10        // words per position in pooling tile (conflict-free LDS64)

// global scratch for pw: [n][g][k][p]
__device__ float g_pw[NN * GG * KK * NPOS];

// ---------- packed f32x2 helpers ----------
__device__ __forceinline__ unsigned long long pk2(float a, float b) {
    unsigned long long r;
    asm("mov.b64 %0, {%1, %2};" : "=l"(r) : "f"(a), "f"(b));
    return r;
}
__device__ __forceinline__ void ffma2(unsigned long long& d, unsigned long long a, unsigned long long b) {
    asm("fma.rn.f32x2 %0, %1, %2, %0;" : "+l"(d) : "l"(a), "l"(b));
}
__device__ __forceinline__ void add2(unsigned long long& d, unsigned long long a) {
    asm("add.rn.f32x2 %0, %0, %1;" : "+l"(d) : "l"(a));
}
__device__ __forceinline__ unsigned long long mul2(unsigned long long a, unsigned long long b) {
    unsigned long long r;
    asm("mul.rn.f32x2 %0, %1, %2;" : "=l"(r) : "l"(a), "l"(b));
    return r;
}
__device__ __forceinline__ float2 upk2(unsigned long long v) {
    float2 r;
    asm("mov.b64 {%0, %1}, %2;" : "=f"(r.x), "=f"(r.y) : "l"(v));
    return r;
}

__device__ __forceinline__ float warp_sum(float v) {
#pragma unroll
    for (int o = 16; o; o >>= 1) v += __shfl_xor_sync(0xffffffffu, v, o);
    return v;
}
__device__ __forceinline__ float warp_max(float v) {
#pragma unroll
    for (int o = 16; o; o >>= 1) v = fmaxf(v, __shfl_xor_sync(0xffffffffu, v, o));
    return v;
}

// swizzled q-tile address: row p, logical float4-group i (0..3)
__device__ __forceinline__ int qaddr(int p, int i) {
    return p * 16 + (((i + (p >> 2)) & 3) << 2);
}

// =====================================================================
// Kernel 1: routing. CTA = (g, n), 704 threads, thread = position p.
// Pool-after-dot: dots computed from raw x (registers); separable
// in-place pooling only for n2; q pooled spatially at the end.
// =====================================================================
__global__ void __launch_bounds__(NPOS, 2) k_route(const float* __restrict__ x,
                                                   const float* __restrict__ lb,
                                                   float* __restrict__ pres_out) {
    const int g = blockIdx.x, n = blockIdx.y;
    const int tid = threadIdx.x;
    const int lane = tid & 31, wid = tid >> 5;

    __shared__ __align__(16) float smem_pool[KK * NPOS];  // 45056 B
    __shared__ float red_s[32];
    __shared__ float colsum_s[KK];
    __shared__ float pinv_s[KK];
    __shared__ float s_emax, s_cnt;

    float* lbn_s = smem_pool;            // [c][k] : 4096 floats
    float* tile  = smem_pool + 4096;     // [p][TILE_STRIDE] : 7040 floats

    // ---- normalize latent basis rows for this g into lbn_s[c*16+k] ----
    if (wid < KK) {
        const float* row = lb + (size_t)(g * KK + wid) * CC;
        float v[8];
        float ss = 0.f;
#pragma unroll
        for (int i = 0; i < 8; i++) { v[i] = row[lane + 32 * i]; ss = fmaf(v[i], v[i], ss); }
        ss = warp_sum(ss);
        float inv = 1.f / fmaxf(sqrtf(ss), 1e-12f);
#pragma unroll
        for (int i = 0; i < 8; i++) lbn_s[(lane + 32 * i) * KK + wid] = v[i] * inv;
    }

    const int p = tid;
    const int ph = p / WW;
    const int pwc = p - ph * WW;
    const float* xbase = x + (size_t)n * CC * CH_STRIDE + (size_t)g * NPOS + p;

    unsigned long long energy2 = 0ULL, n22 = 0ULL;
    unsigned long long dot2[8];
#pragma unroll
    for (int j = 0; j < 8; j++) dot2[j] = 0ULL;

    const bool hasL = (pwc > 0), hasR = (pwc < WW - 1);
    const bool hasU = (ph > 0),  hasD = (ph < HS - 1);
    float* mybase = tile + p * TILE_STRIDE;
    const unsigned long long ninth = pk2(1.f / 9.f, 1.f / 9.f);

    // prefetch batch 0 (4 channel-pairs)
    float2 v[4];
#pragma unroll
    for (int j = 0; j < 4; j++) {
        v[j].x = xbase[(size_t)(2 * j)     * CH_STRIDE];
        v[j].y = xbase[(size_t)(2 * j + 1) * CH_STRIDE];
    }

    for (int b = 0; b < CC / 8; b++) {
        __syncthreads();                 // S1: prior batch vertical reads done
#pragma unroll
        for (int j = 0; j < 4; j++)
            *(float2*)(mybase + 2 * j) = v[j];
        __syncthreads();                 // S2: v tile visible

        // hsum from tile neighbors (center from regs), interleaved with
        // dots + energy (pure register / broadcast-smem work).
        unsigned long long hreg[4];
#pragma unroll
        for (int j = 0; j < 4; j++) {
            const int off = 2 * j;
            unsigned long long cen = pk2(v[j].x, v[j].y);
            unsigned long long h = cen;
            if (hasL) add2(h, *(const unsigned long long*)(mybase - TILE_STRIDE + off));
            if (hasR) add2(h, *(const unsigned long long*)(mybase + TILE_STRIDE + off));
            hreg[j] = h;

            ffma2(energy2, cen, cen);

            unsigned long long pa = pk2(v[j].x, v[j].x);
            unsigned long long pb = pk2(v[j].y, v[j].y);
            const int c0 = b * 8 + 2 * j;
            const ulonglong2* l0 = (const ulonglong2*)(lbn_s + c0 * KK);
            {
                ulonglong2 q0 = l0[0], q1 = l0[1], q2 = l0[2], q3 = l0[3];
                ffma2(dot2[0], pa, q0.x); ffma2(dot2[1], pa, q0.y);
                ffma2(dot2[2], pa, q1.x); ffma2(dot2[3], pa, q1.y);
                ffma2(dot2[4], pa, q2.x); ffma2(dot2[5], pa, q2.y);
                ffma2(dot2[6], pa, q3.x); ffma2(dot2[7], pa, q3.y);
            }
            {
                ulonglong2 q0 = l0[4], q1 = l0[5], q2 = l0[6], q3 = l0[7];
                ffma2(dot2[0], pb, q0.x); ffma2(dot2[1], pb, q0.y);
                ffma2(dot2[2], pb, q1.x); ffma2(dot2[3], pb, q1.y);
                ffma2(dot2[4], pb, q2.x); ffma2(dot2[5], pb, q2.y);
                ffma2(dot2[6], pb, q3.x); ffma2(dot2[7], pb, q3.y);
            }
        }

        // v regs dead now -> prefetch next batch (long latency window)
        if (b < CC / 8 - 1) {
            const float* nb = xbase + (size_t)(b + 1) * 8 * CH_STRIDE;
#pragma unroll
            for (int j = 0; j < 4; j++) {
                v[j].x = nb[(size_t)(2 * j)     * CH_STRIDE];
                v[j].y = nb[(size_t)(2 * j + 1) * CH_STRIDE];
            }
        }

        __syncthreads();                 // S3: all v reads complete
#pragma unroll
        for (int j = 0; j < 4; j++)
            *(unsigned long long*)(mybase + 2 * j) = hreg[j];
        __syncthreads();                 // S4: hsum tile visible

        // vertical pass -> pooled, accumulate n2
#pragma unroll
        for (int j = 0; j < 4; j++) {
            const int off = 2 * j;
            unsigned long long s = hreg[j];
            if (hasU) add2(s, *(const unsigned long long*)(mybase - WW * TILE_STRIDE + off));
            if (hasD) add2(s, *(const unsigned long long*)(mybase + WW * TILE_STRIDE + off));
            unsigned long long pooled2 = mul2(s, ninth);
            ffma2(n22, pooled2, pooled2);
        }
    }

    float2 et = upk2(energy2);
    float energy = et.x + et.y;
    float2 nt = upk2(n22);
    float n2 = nt.x + nt.y;

    // =========== spatial 3x3 pool of q (dot2), separable, swizzled ===========
    float* qt = smem_pool;   // reuse (lbn + vtile dead)
    __syncthreads();         // all vertical reads done before overwrite
#pragma unroll
    for (int i = 0; i < 4; i++) {
        ulonglong2 qq; qq.x = dot2[2 * i]; qq.y = dot2[2 * i + 1];
        *(ulonglong2*)(qt + qaddr(p, i)) = qq;
    }
    __syncthreads();
    // horizontal pass (into dot2)
#pragma unroll
    for (int i = 0; i < 4; i++) {
        if (hasL) {
            ulonglong2 L = *(const ulonglong2*)(qt + qaddr(p - 1, i));
            add2(dot2[2 * i], L.x); add2(dot2[2 * i + 1], L.y);
        }
        if (hasR) {
            ulonglong2 R = *(const ulonglong2*)(qt + qaddr(p + 1, i));
            add2(dot2[2 * i], R.x); add2(dot2[2 * i + 1], R.y);
        }
    }
    __syncthreads();         // all q reads done
#pragma unroll
    for (int i = 0; i < 4; i++) {
        ulonglong2 qq; qq.x = dot2[2 * i]; qq.y = dot2[2 * i + 1];
        *(ulonglong2*)(qt + qaddr(p, i)) = qq;
    }
    __syncthreads();
    // vertical pass
#pragma unroll
    for (int i = 0; i < 4; i++) {
        if (hasU) {
            ulonglong2 U = *(const ulonglong2*)(qt + qaddr(p - WW, i));
            add2(dot2[2 * i], U.x); add2(dot2[2 * i + 1], U.y);
        }
        if (hasD) {
            ulonglong2 D = *(const ulonglong2*)(qt + qaddr(p + WW, i));
            add2(dot2[2 * i], D.x); add2(dot2[2 * i + 1], D.y);
        }
    }
    __syncthreads();         // hq reads done (qt free for supp)

    // ---- energy max over block ----
    float wm = warp_max(energy);
    if (lane == 0) red_s[wid] = wm;
    __syncthreads();
    if (tid == 0) {
        float m = red_s[0];
        for (int w = 1; w < 22; w++) m = fmaxf(m, red_s[w]);
        s_emax = m;
    }
    __syncthreads();

    float denom = fmaxf(s_emax * (1.f / 256.f), EPSV);
    float en = (energy * (1.f / 256.f)) / denom;
    bool amb = en > GATE;

    float cw = warp_sum(amb ? 1.f : 0.f);
    if (lane == 0) red_s[wid] = cw;
    __syncthreads();
    if (tid == 0) {
        float m = 0.f;
        for (int w = 0; w < 22; w++) m += red_s[w];
        s_cnt = m;
    }
    __syncthreads();
    if (s_cnt <= 0.f) amb = (energy > 0.f);
    float am_f = amb ? 1.f : 0.f;

    // ---- logits -> softmax -> supp (registers) ----
    // dot2 currently holds 9*pooled_dot; fold the 1/9 into the scale.
    float d[KK];
#pragma unroll
    for (int j = 0; j < 8; j++) {
        float2 t = upk2(dot2[j]);
        d[2 * j] = t.x;
        d[2 * j + 1] = t.y;
    }
    float inv = (8.f / 9.f) / fmaxf(sqrtf(n2), 1e-12f);   // 1/TEMP=8, pool 1/9
    float mx = -1e30f;
#pragma unroll
    for (int k = 0; k < KK; k++) { d[k] = d[k] * inv; mx = fmaxf(mx, d[k]); }
    float se = 0.f;
#pragma unroll
    for (int k = 0; k < KK; k++) { d[k] = __expf(d[k] - mx); se += d[k]; }
    float sc = am_f / se;   // supp[k] = d[k]*sc

    float* supp_s = smem_pool;   // reuse
#pragma unroll
    for (int k = 0; k < KK; k++) supp_s[k * NPOS + p] = d[k] * sc;
    __syncthreads();

    // ---- per-k: colsum + exact top-88 presence (warp k owns column k) ----
    if (wid < KK) {
        float vals[22];
        float s = 0.f;
#pragma unroll
        for (int i = 0; i < 22; i++) {
            vals[i] = supp_s[wid * NPOS + lane + 32 * i];
            s += vals[i];
        }
        s = warp_sum(s);
        if (lane == 0) colsum_s[wid] = s;

        // binary search on nonneg float bit patterns for 88th largest
        unsigned V = 0u;
        for (int bit = 30; bit >= 0; --bit) {
            unsigned cand = V | (1u << bit);
            float cf = __uint_as_float(cand);
            int cnt = 0;
#pragma unroll
            for (int i = 0; i < 22; i++) cnt += (vals[i] >= cf) ? 1 : 0;
            cnt = __reduce_add_sync(0xffffffffu, cnt);
            if (cnt >= TOPK) V = cand;
        }
        float kth = __uint_as_float(V);
        int cgt = 0;
        float sgt = 0.f;
#pragma unroll
        for (int i = 0; i < 22; i++) {
            if (vals[i] > kth) { cgt++; sgt += vals[i]; }
        }
        cgt = __reduce_add_sync(0xffffffffu, cgt);
        sgt = warp_sum(sgt);
        if (lane == 0) {
            float pr = (sgt + kth * (float)(TOPK - cgt)) * (1.f / (float)TOPK);
            pres_out[n * (GG * KK) + g * KK + wid] = pr;
        }
    }
    __syncthreads();
    if (tid < KK) pinv_s[tid] = 1.f / fmaxf(colsum_s[tid], EPSV);
    __syncthreads();

    // ---- pw = supp / colsum -> global scratch ----
    float* gpw = g_pw + (size_t)(n * GG + g) * KK * NPOS;
#pragma unroll
    for (int k = 0; k < KK; k++) gpw[k * NPOS + p] = d[k] * sc * pinv_s[k];
}

// =====================================================================
// Kernel 2: tokens[k][c] = sum_p pw[p][k] * x[c][p].  CTA = (g, n),
// 128 threads, thread = channels (c, c+128). x staged through smem in
// 32-position chunks (coalesced LDG); pw read as uniform L1-hit LDG.
// =====================================================================
#define PCH 32               // positions per chunk
#define NCHUNK 22            // 704/32
#define XS_STRIDE 36         // floats per channel row in x_s (9 float4, N=2)

__global__ void __launch_bounds__(128) k_tokens(const float* __restrict__ x,
                                                float* __restrict__ out) {
    const int g = blockIdx.x, n = blockIdx.y;
    __shared__ __align__(16) float x_s[CC * XS_STRIDE];   // 36864 B

    const int tid = threadIdx.x;
    const float* xg = x + (size_t)n * CC * CH_STRIDE + (size_t)g * NPOS;
    const ulonglong2* pw2 = (const ulonglong2*)(g_pw + (size_t)(n * GG + g) * KK * NPOS);

    const int c0 = tid;
    const int c1 = tid + 128;

    unsigned long long accA[KK], accB[KK];
#pragma unroll
    for (int k = 0; k < KK; k++) { accA[k] = 0ULL; accB[k] = 0ULL; }

    for (int ch = 0; ch < NCHUNK; ch++) {
        const int p0 = ch * PCH;
        __syncthreads();   // prior chunk's x_s reads done
        // stage 256 channels x 32 positions, coalesced
#pragma unroll
        for (int it = 0; it < 16; it++) {
            int f = tid + 128 * it;          // 0..2047
            int c = f >> 3, i = f & 7;
            float4 vv = __ldg((const float4*)(xg + (size_t)c * CH_STRIDE + p0) + i);
            *(float4*)(x_s + c * XS_STRIDE + i * 4) = vv;
        }
        __syncthreads();

        const int p4base = ch * (PCH / 4);
#pragma unroll
        for (int i = 0; i < 8; i++) {
            float4 xa = *(const float4*)(x_s + c0 * XS_STRIDE + i * 4);
            float4 xb = *(const float4*)(x_s + c1 * XS_STRIDE + i * 4);
            unsigned long long alo = pk2(xa.x, xa.y);
            unsigned long long ahi = pk2(xa.z, xa.w);
            unsigned long long blo = pk2(xb.x, xb.y);
            unsigned long long bhi = pk2(xb.z, xb.w);
            const ulonglong2* pwrow = pw2 + (p4base + i);
#pragma unroll
            for (int k = 0; k < KK; k++) {
                ulonglong2 pv = pwrow[k * NPOS4];   // uniform across warp, L1-hit
                ffma2(accA[k], alo, pv.x);
                ffma2(accA[k], ahi, pv.y);
                ffma2(accB[k], blo, pv.x);
                ffma2(accB[k], bhi, pv.y);
            }
        }
    }

    float resA[KK], resB[KK];
#pragma unroll
    for (int k = 0; k < KK; k++) {
        float2 ta = upk2(accA[k]);
        resA[k] = ta.x + ta.y;
        float2 tb = upk2(accB[k]);
        resB[k] = tb.x + tb.y;
    }
    float4* oa = (float4*)(out + (size_t)(n * CC + c0) * (GG * KK) + g * KK);
    oa[0] = make_float4(resA[0], resA[1], resA[2], resA[3]);
    oa[1] = make_float4(resA[4], resA[5], resA[6], resA[7]);
    oa[2] = make_float4(resA[8], resA[9], resA[10], resA[11]);
    oa[3] = make_float4(resA[12], resA[13], resA[14], resA[15]);
    float4* ob = (float4*)(out + (size_t)(n * CC + c1) * (GG * KK) + g * KK);
    ob[0] = make_float4(resB[0], resB[1], resB[2], resB[3]);
    ob[1] = make_float4(resB[4], resB[5], resB[6], resB[7]);
    ob[2] = make_float4(resB[8], resB[9], resB[10], resB[11]);
    ob[3] = make_float4(resB[12], resB[13], resB[14], resB[15]);
}

// =====================================================================
// Kernel 3: normalize presence per n (in place).
// =====================================================================
__global__ void k_presnorm(float* __restrict__ pres) {
    const int n = blockIdx.x;
    const int t = threadIdx.x;
    float v = pres[n * 64 + t];
    float s = warp_sum(v);
    __shared__ float sh[2];
    if ((t & 31) == 0) sh[t >> 5] = s;
    __syncthreads();
    float tot = sh[0] + sh[1];
    pres[n * 64 + t] = v / fmaxf(tot, EPSV);
}

extern "C" void kernel_launch(void* const* d_in, const int* in_sizes, int n_in,
                              void* d_out, int out_size) {
    const float* x = (const float*)d_in[0];
    const float* lb = (const float*)d_in[1];
    float* out = (float*)d_out;
    float* pres = out + (size_t)NN * CC * (GG * KK);   // tokens first, then pres

    dim3 grid(GG, NN);
    k_route<<<grid, NPOS>>>(x, lb, pres);
    k_tokens<<<grid, 128>>>(x, out);
    k_presnorm<<<NN, 64>>>(pres);
}

// round 10
// speedup vs baseline: 1.2486x; 1.2486x over previous
#include <cuda_runtime.h>
#include <cstdint>

// Problem constants
#define NN 64
#define CC 256
#define GG 4
#define HS 16
#define WW 44
#define KK 16
#define NPOS 704              // HS*WW
#define NPOS4 176             // NPOS/4
#define TOPK 88               // int(704*0.125)
#define GATE 0.05f
#define EPSV 1e-6f
#define CH_STRIDE 2816        // GG*NPOS, channel stride in floats
#define TILE_STRIDE 10        // words per position in pooling tile (conflict-free LDS64)

// global scratch for pw: [n][g][k][p]
__device__ float g_pw[NN * GG * KK * NPOS];

// ---------- packed f32x2 helpers ----------
__device__ __forceinline__ unsigned long long pk2(float a, float b) {
    unsigned long long r;
    asm("mov.b64 %0, {%1, %2};" : "=l"(r) : "f"(a), "f"(b));
    return r;
}
__device__ __forceinline__ void ffma2(unsigned long long& d, unsigned long long a, unsigned long long b) {
    asm("fma.rn.f32x2 %0, %1, %2, %0;" : "+l"(d) : "l"(a), "l"(b));
}
__device__ __forceinline__ void add2(unsigned long long& d, unsigned long long a) {
    asm("add.rn.f32x2 %0, %0, %1;" : "+l"(d) : "l"(a));
}
__device__ __forceinline__ unsigned long long mul2(unsigned long long a, unsigned long long b) {
    unsigned long long r;
    asm("mul.rn.f32x2 %0, %1, %2;" : "=l"(r) : "l"(a), "l"(b));
    return r;
}
__device__ __forceinline__ float2 upk2(unsigned long long v) {
    float2 r;
    asm("mov.b64 {%0, %1}, %2;" : "=f"(r.x), "=f"(r.y) : "l"(v));
    return r;
}

__device__ __forceinline__ float warp_sum(float v) {
#pragma unroll
    for (int o = 16; o; o >>= 1) v += __shfl_xor_sync(0xffffffffu, v, o);
    return v;
}
__device__ __forceinline__ float warp_max(float v) {
#pragma unroll
    for (int o = 16; o; o >>= 1) v = fmaxf(v, __shfl_xor_sync(0xffffffffu, v, o));
    return v;
}

// =====================================================================
// Kernel 1: routing. CTA = (g, n), 704 threads, thread = position p.
// 8 channels (4 pairs) per barrier phase; pooling in packed f32x2.
// (Exact R7 structure — known 181us.)
// =====================================================================
__global__ void __launch_bounds__(NPOS, 2) k_route(const float* __restrict__ x,
                                                   const float* __restrict__ lb,
                                                   float* __restrict__ pres_out) {
    const int g = blockIdx.x, n = blockIdx.y;
    const int tid = threadIdx.x;
    const int lane = tid & 31, wid = tid >> 5;

    __shared__ __align__(16) float smem_pool[KK * NPOS];  // 45056 B
    __shared__ float red_s[32];
    __shared__ float colsum_s[KK];
    __shared__ float pinv_s[KK];
    __shared__ float s_emax, s_cnt;

    float* lbn_s = smem_pool;            // [c][k] : 4096 floats
    float* tile  = smem_pool + 4096;     // [p][TILE_STRIDE] : 7040 floats

    // ---- normalize latent basis rows for this g into lbn_s[c*16+k] ----
    if (wid < KK) {
        const float* row = lb + (size_t)(g * KK + wid) * CC;
        float v[8];
        float ss = 0.f;
#pragma unroll
        for (int i = 0; i < 8; i++) { v[i] = row[lane + 32 * i]; ss = fmaf(v[i], v[i], ss); }
        ss = warp_sum(ss);
        float inv = 1.f / fmaxf(sqrtf(ss), 1e-12f);
#pragma unroll
        for (int i = 0; i < 8; i++) lbn_s[(lane + 32 * i) * KK + wid] = v[i] * inv;
    }

    const int p = tid;
    const int ph = p / WW;
    const int pwc = p - ph * WW;
    const float* xbase = x + (size_t)n * CC * CH_STRIDE + (size_t)g * NPOS + p;

    unsigned long long energy2 = 0ULL, n22 = 0ULL;
    unsigned long long dot2[8];
#pragma unroll
    for (int j = 0; j < 8; j++) dot2[j] = 0ULL;

    const bool hasL = (pwc > 0), hasR = (pwc < WW - 1);
    const bool hasU = (ph > 0),  hasD = (ph < HS - 1);
    float* mybase = tile + p * TILE_STRIDE;

    // prefetch batch 0 (4 channel-pairs)
    float2 v[4];
#pragma unroll
    for (int j = 0; j < 4; j++) {
        v[j].x = xbase[(size_t)(2 * j)     * CH_STRIDE];
        v[j].y = xbase[(size_t)(2 * j + 1) * CH_STRIDE];
    }

    for (int b = 0; b < CC / 8; b++) {
        __syncthreads();   // previous batch's tile reads complete
#pragma unroll
        for (int j = 0; j < 4; j++)
            *(float2*)(mybase + 2 * j) = v[j];
        __syncthreads();   // tile visible

        // prefetch next batch (8-deep MLP overlapped with pooling compute)
        if (b < CC / 8 - 1) {
            const float* nb = xbase + (size_t)(b + 1) * 8 * CH_STRIDE;
#pragma unroll
            for (int j = 0; j < 4; j++) {
                v[j].x = nb[(size_t)(2 * j)     * CH_STRIDE];
                v[j].y = nb[(size_t)(2 * j + 1) * CH_STRIDE];
            }
        }

#pragma unroll
        for (int j = 0; j < 4; j++) {
            const int off = 2 * j;
            unsigned long long cen = *(const unsigned long long*)(mybase + off);
            unsigned long long s = cen;
            if (hasL) add2(s, *(const unsigned long long*)(mybase - TILE_STRIDE + off));
            if (hasR) add2(s, *(const unsigned long long*)(mybase + TILE_STRIDE + off));
            if (hasU) {
                const float* up = mybase - WW * TILE_STRIDE + off;
                add2(s, *(const unsigned long long*)up);
                if (hasL) add2(s, *(const unsigned long long*)(up - TILE_STRIDE));
                if (hasR) add2(s, *(const unsigned long long*)(up + TILE_STRIDE));
            }
            if (hasD) {
                const float* dn = mybase + WW * TILE_STRIDE + off;
                add2(s, *(const unsigned long long*)dn);
                if (hasL) add2(s, *(const unsigned long long*)(dn - TILE_STRIDE));
                if (hasR) add2(s, *(const unsigned long long*)(dn + TILE_STRIDE));
            }
            unsigned long long ninth = pk2(1.f / 9.f, 1.f / 9.f);
            unsigned long long pooled2 = mul2(s, ninth);

            ffma2(energy2, cen, cen);
            ffma2(n22, pooled2, pooled2);

            float2 pf = upk2(pooled2);
            unsigned long long pa = pk2(pf.x, pf.x);
            unsigned long long pb = pk2(pf.y, pf.y);
            const int c0 = b * 8 + 2 * j;
            const ulonglong2* l0 = (const ulonglong2*)(lbn_s + c0 * KK);
            // channel c0
            {
                ulonglong2 q0 = l0[0], q1 = l0[1], q2 = l0[2], q3 = l0[3];
                ffma2(dot2[0], pa, q0.x); ffma2(dot2[1], pa, q0.y);
                ffma2(dot2[2], pa, q1.x); ffma2(dot2[3], pa, q1.y);
                ffma2(dot2[4], pa, q2.x); ffma2(dot2[5], pa, q2.y);
                ffma2(dot2[6], pa, q3.x); ffma2(dot2[7], pa, q3.y);
            }
            // channel c0+1
            {
                ulonglong2 q0 = l0[4], q1 = l0[5], q2 = l0[6], q3 = l0[7];
                ffma2(dot2[0], pb, q0.x); ffma2(dot2[1], pb, q0.y);
                ffma2(dot2[2], pb, q1.x); ffma2(dot2[3], pb, q1.y);
                ffma2(dot2[4], pb, q2.x); ffma2(dot2[5], pb, q2.y);
                ffma2(dot2[6], pb, q3.x); ffma2(dot2[7], pb, q3.y);
            }
        }
    }

    float2 et = upk2(energy2);
    float energy = et.x + et.y;
    float2 nt = upk2(n22);
    float n2 = nt.x + nt.y;

    __syncthreads();

    // ---- energy max over block ----
    float wm = warp_max(energy);
    if (lane == 0) red_s[wid] = wm;
    __syncthreads();
    if (tid == 0) {
        float m = red_s[0];
        for (int w = 1; w < 22; w++) m = fmaxf(m, red_s[w]);
        s_emax = m;
    }
    __syncthreads();

    float denom = fmaxf(s_emax * (1.f / 256.f), EPSV);
    float en = (energy * (1.f / 256.f)) / denom;
    bool amb = en > GATE;

    float cw = warp_sum(amb ? 1.f : 0.f);
    if (lane == 0) red_s[wid] = cw;
    __syncthreads();
    if (tid == 0) {
        float m = 0.f;
        for (int w = 0; w < 22; w++) m += red_s[w];
        s_cnt = m;
    }
    __syncthreads();
    if (s_cnt <= 0.f) amb = (energy > 0.f);
    float am_f = amb ? 1.f : 0.f;

    // ---- logits -> softmax -> supp (registers) ----
    float d[KK];
#pragma unroll
    for (int j = 0; j < 8; j++) {
        float2 t = upk2(dot2[j]);
        d[2 * j] = t.x;
        d[2 * j + 1] = t.y;
    }
    float inv = 1.f / fmaxf(sqrtf(n2), 1e-12f);
    float mx = -1e30f;
#pragma unroll
    for (int k = 0; k < KK; k++) { d[k] = d[k] * inv * 8.f; mx = fmaxf(mx, d[k]); }
    float se = 0.f;
#pragma unroll
    for (int k = 0; k < KK; k++) { d[k] = __expf(d[k] - mx); se += d[k]; }
    float sc = am_f / se;   // supp[k] = d[k]*sc

    float* supp_s = smem_pool;   // reuse (lbn/tile done)
#pragma unroll
    for (int k = 0; k < KK; k++) supp_s[k * NPOS + p] = d[k] * sc;
    __syncthreads();

    // ---- per-k: colsum + exact top-88 presence (warp k owns column k) ----
    if (wid < KK) {
        float vals[22];
        float s = 0.f;
#pragma unroll
        for (int i = 0; i < 22; i++) {
            vals[i] = supp_s[wid * NPOS + lane + 32 * i];
            s += vals[i];
        }
        s = warp_sum(s);
        if (lane == 0) colsum_s[wid] = s;

        // binary search on nonneg float bit patterns for 88th largest
        unsigned V = 0u;
        for (int bit = 30; bit >= 0; --bit) {
            unsigned cand = V | (1u << bit);
            float cf = __uint_as_float(cand);
            int cnt = 0;
#pragma unroll
            for (int i = 0; i < 22; i++) cnt += (vals[i] >= cf) ? 1 : 0;
            cnt = __reduce_add_sync(0xffffffffu, cnt);
            if (cnt >= TOPK) V = cand;
        }
        float kth = __uint_as_float(V);
        int cgt = 0;
        float sgt = 0.f;
#pragma unroll
        for (int i = 0; i < 22; i++) {
            if (vals[i] > kth) { cgt++; sgt += vals[i]; }
        }
        cgt = __reduce_add_sync(0xffffffffu, cgt);
        sgt = warp_sum(sgt);
        if (lane == 0) {
            float pr = (sgt + kth * (float)(TOPK - cgt)) * (1.f / (float)TOPK);
            pres_out[n * (GG * KK) + g * KK + wid] = pr;
        }
    }
    __syncthreads();
    if (tid < KK) pinv_s[tid] = 1.f / fmaxf(colsum_s[tid], EPSV);
    __syncthreads();

    // ---- pw = supp / colsum -> global scratch ----
    float* gpw = g_pw + (size_t)(n * GG + g) * KK * NPOS;
#pragma unroll
    for (int k = 0; k < KK; k++) gpw[k * NPOS + p] = d[k] * sc * pinv_s[k];
}

// =====================================================================
// Kernel 2: tokens[k][c] = sum_p pw[p][k] * x[c][p].  CTA = (g, n),
// 512 threads. Warp = 4 channels (cg = lane>>3) x 8 position-lanes
// (pl = lane&7): x LDG.128 touches 4 contiguous 128B lines (4 wf, not
// 32); pw LDS128 is 8-lane-contiguous + 4-group broadcast (1 wf).
// Partial dots reduced over pl lanes via 3 shfl steps.
// =====================================================================
__global__ void __launch_bounds__(512) k_tokens(const float* __restrict__ x,
                                                float* __restrict__ out) {
    const int g = blockIdx.x, n = blockIdx.y;
    __shared__ __align__(16) float pw_s[KK * NPOS];   // 45056 B

    const int tid = threadIdx.x;
    {
        const float4* src = (const float4*)(g_pw + (size_t)(n * GG + g) * KK * NPOS);
        float4* dst = (float4*)pw_s;
        for (int i = tid; i < KK * NPOS4; i += 512) dst[i] = src[i];
    }
    __syncthreads();

    const int warp = tid >> 5, lane = tid & 31;
    const int cg = lane >> 3, pl = lane & 7;
    const float* xg = x + (size_t)n * CC * CH_STRIDE + (size_t)g * NPOS;

#pragma unroll
    for (int pass = 0; pass < 4; pass++) {
        const int c = pass * 64 + warp * 4 + cg;
        const float4* x4 = (const float4*)(xg + (size_t)c * CH_STRIDE);

        unsigned long long acc[KK];
#pragma unroll
        for (int k = 0; k < KK; k++) acc[k] = 0ULL;

#pragma unroll 2
        for (int i = 0; i < 22; i++) {
            const int pi4 = pl + 8 * i;
            float4 xv = __ldg(x4 + pi4);
            unsigned long long xlo = pk2(xv.x, xv.y);
            unsigned long long xhi = pk2(xv.z, xv.w);
#pragma unroll
            for (int k = 0; k < KK; k++) {
                ulonglong2 pv = *(const ulonglong2*)(pw_s + k * NPOS + 4 * pi4);
                ffma2(acc[k], xlo, pv.x);
                ffma2(acc[k], xhi, pv.y);
            }
        }

        float res[KK];
#pragma unroll
        for (int k = 0; k < KK; k++) {
            float2 t = upk2(acc[k]);
            float s = t.x + t.y;
            s += __shfl_xor_sync(0xffffffffu, s, 4);
            s += __shfl_xor_sync(0xffffffffu, s, 2);
            s += __shfl_xor_sync(0xffffffffu, s, 1);
            res[k] = s;
        }
        if (pl == 0) {
            float4* o = (float4*)(out + (size_t)(n * CC + c) * (GG * KK) + g * KK);
            o[0] = make_float4(res[0], res[1], res[2], res[3]);
            o[1] = make_float4(res[4], res[5], res[6], res[7]);
            o[2] = make_float4(res[8], res[9], res[10], res[11]);
            o[3] = make_float4(res[12], res[13], res[14], res[15]);
        }
    }
}

// =====================================================================
// Kernel 3: normalize presence per n (in place).
// =====================================================================
__global__ void k_presnorm(float* __restrict__ pres) {
    const int n = blockIdx.x;
    const int t = threadIdx.x;
    float v = pres[n * 64 + t];
    float s = warp_sum(v);
    __shared__ float sh[2];
    if ((t & 31) == 0) sh[t >> 5] = s;
    __syncthreads();
    float tot = sh[0] + sh[1];
    pres[n * 64 + t] = v / fmaxf(tot, EPSV);
}

extern "C" void kernel_launch(void* const* d_in, const int* in_sizes, int n_in,
                              void* d_out, int out_size) {
    const float* x = (const float*)d_in[0];
    const float* lb = (const float*)d_in[1];
    float* out = (float*)d_out;
    float* pres = out + (size_t)NN * CC * (GG * KK);   // tokens first, then pres

    dim3 grid(GG, NN);
    k_route<<<grid, NPOS>>>(x, lb, pres);
    k_tokens<<<grid, 512>>>(x, out);
    k_presnorm<<<NN, 64>>>(pres);
}

// round 12
// speedup vs baseline: 1.4953x; 1.1975x over previous
#include <cuda_runtime.h>
#include <cstdint>

// Problem constants
#define NN 64
#define CC 256
#define GG 4
#define HS 16
#define WW 44
#define KK 16
#define NPOS 704              // HS*WW
#define NPOS4 176             // NPOS/4
#define TOPK 88               // int(704*0.125)
#define GATE 0.05f
#define EPSV 1e-6f
#define CH_STRIDE 2816        // GG*NPOS, channel stride in floats
#define TILE_STRIDE 10        // words per position in pooling tile (conflict-free LDS64)

// global scratch for pw: [n][g][k][p]
__device__ float g_pw[NN * GG * KK * NPOS];

// ---------- packed f32x2 helpers ----------
__device__ __forceinline__ unsigned long long pk2(float a, float b) {
    unsigned long long r;
    asm("mov.b64 %0, {%1, %2};" : "=l"(r) : "f"(a), "f"(b));
    return r;
}
__device__ __forceinline__ void ffma2(unsigned long long& d, unsigned long long a, unsigned long long b) {
    asm("fma.rn.f32x2 %0, %1, %2, %0;" : "+l"(d) : "l"(a), "l"(b));
}
__device__ __forceinline__ void add2(unsigned long long& d, unsigned long long a) {
    asm("add.rn.f32x2 %0, %0, %1;" : "+l"(d) : "l"(a));
}
__device__ __forceinline__ unsigned long long mul2(unsigned long long a, unsigned long long b) {
    unsigned long long r;
    asm("mul.rn.f32x2 %0, %1, %2;" : "=l"(r) : "l"(a), "l"(b));
    return r;
}
__device__ __forceinline__ float2 upk2(unsigned long long v) {
    float2 r;
    asm("mov.b64 {%0, %1}, %2;" : "=f"(r.x), "=f"(r.y) : "l"(v));
    return r;
}

__device__ __forceinline__ float warp_sum(float v) {
#pragma unroll
    for (int o = 16; o; o >>= 1) v += __shfl_xor_sync(0xffffffffu, v, o);
    return v;
}
__device__ __forceinline__ float warp_max(float v) {
#pragma unroll
    for (int o = 16; o; o >>= 1) v = fmaxf(v, __shfl_xor_sync(0xffffffffu, v, o));
    return v;
}

// =====================================================================
// Kernel 1: routing. CTA = (g, n), 704 threads, thread = position p.
// 8 channels (4 pairs) per barrier phase; pooling in packed f32x2.
// (Exact R7 structure — measured 180us.)
// =====================================================================
__global__ void __launch_bounds__(NPOS, 2) k_route(const float* __restrict__ x,
                                                   const float* __restrict__ lb,
                                                   float* __restrict__ pres_out) {
    const int g = blockIdx.x, n = blockIdx.y;
    const int tid = threadIdx.x;
    const int lane = tid & 31, wid = tid >> 5;

    __shared__ __align__(16) float smem_pool[KK * NPOS];  // 45056 B
    __shared__ float red_s[32];
    __shared__ float colsum_s[KK];
    __shared__ float pinv_s[KK];
    __shared__ float s_emax, s_cnt;

    float* lbn_s = smem_pool;            // [c][k] : 4096 floats
    float* tile  = smem_pool + 4096;     // [p][TILE_STRIDE] : 7040 floats

    // ---- normalize latent basis rows for this g into lbn_s[c*16+k] ----
    if (wid < KK) {
        const float* row = lb + (size_t)(g * KK + wid) * CC;
        float v[8];
        float ss = 0.f;
#pragma unroll
        for (int i = 0; i < 8; i++) { v[i] = row[lane + 32 * i]; ss = fmaf(v[i], v[i], ss); }
        ss = warp_sum(ss);
        float inv = 1.f / fmaxf(sqrtf(ss), 1e-12f);
#pragma unroll
        for (int i = 0; i < 8; i++) lbn_s[(lane + 32 * i) * KK + wid] = v[i] * inv;
    }

    const int p = tid;
    const int ph = p / WW;
    const int pwc = p - ph * WW;
    const float* xbase = x + (size_t)n * CC * CH_STRIDE + (size_t)g * NPOS + p;

    unsigned long long energy2 = 0ULL, n22 = 0ULL;
    unsigned long long dot2[8];
#pragma unroll
    for (int j = 0; j < 8; j++) dot2[j] = 0ULL;

    const bool hasL = (pwc > 0), hasR = (pwc < WW - 1);
    const bool hasU = (ph > 0),  hasD = (ph < HS - 1);
    float* mybase = tile + p * TILE_STRIDE;

    // prefetch batch 0 (4 channel-pairs)
    float2 v[4];
#pragma unroll
    for (int j = 0; j < 4; j++) {
        v[j].x = xbase[(size_t)(2 * j)     * CH_STRIDE];
        v[j].y = xbase[(size_t)(2 * j + 1) * CH_STRIDE];
    }

    for (int b = 0; b < CC / 8; b++) {
        __syncthreads();   // previous batch's tile reads complete
#pragma unroll
        for (int j = 0; j < 4; j++)
            *(float2*)(mybase + 2 * j) = v[j];
        __syncthreads();   // tile visible

        // prefetch next batch (8-deep MLP overlapped with pooling compute)
        if (b < CC / 8 - 1) {
            const float* nb = xbase + (size_t)(b + 1) * 8 * CH_STRIDE;
#pragma unroll
            for (int j = 0; j < 4; j++) {
                v[j].x = nb[(size_t)(2 * j)     * CH_STRIDE];
                v[j].y = nb[(size_t)(2 * j + 1) * CH_STRIDE];
            }
        }

#pragma unroll
        for (int j = 0; j < 4; j++) {
            const int off = 2 * j;
            unsigned long long cen = *(const unsigned long long*)(mybase + off);
            unsigned long long s = cen;
            if (hasL) add2(s, *(const unsigned long long*)(mybase - TILE_STRIDE + off));
            if (hasR) add2(s, *(const unsigned long long*)(mybase + TILE_STRIDE + off));
            if (hasU) {
                const float* up = mybase - WW * TILE_STRIDE + off;
                add2(s, *(const unsigned long long*)up);
                if (hasL) add2(s, *(const unsigned long long*)(up - TILE_STRIDE));
                if (hasR) add2(s, *(const unsigned long long*)(up + TILE_STRIDE));
            }
            if (hasD) {
                const float* dn = mybase + WW * TILE_STRIDE + off;
                add2(s, *(const unsigned long long*)dn);
                if (hasL) add2(s, *(const unsigned long long*)(dn - TILE_STRIDE));
                if (hasR) add2(s, *(const unsigned long long*)(dn + TILE_STRIDE));
            }
            unsigned long long ninth = pk2(1.f / 9.f, 1.f / 9.f);
            unsigned long long pooled2 = mul2(s, ninth);

            ffma2(energy2, cen, cen);
            ffma2(n22, pooled2, pooled2);

            float2 pf = upk2(pooled2);
            unsigned long long pa = pk2(pf.x, pf.x);
            unsigned long long pb = pk2(pf.y, pf.y);
            const int c0 = b * 8 + 2 * j;
            const ulonglong2* l0 = (const ulonglong2*)(lbn_s + c0 * KK);
            // channel c0
            {
                ulonglong2 q0 = l0[0], q1 = l0[1], q2 = l0[2], q3 = l0[3];
                ffma2(dot2[0], pa, q0.x); ffma2(dot2[1], pa, q0.y);
                ffma2(dot2[2], pa, q1.x); ffma2(dot2[3], pa, q1.y);
                ffma2(dot2[4], pa, q2.x); ffma2(dot2[5], pa, q2.y);
                ffma2(dot2[6], pa, q3.x); ffma2(dot2[7], pa, q3.y);
            }
            // channel c0+1
            {
                ulonglong2 q0 = l0[4], q1 = l0[5], q2 = l0[6], q3 = l0[7];
                ffma2(dot2[0], pb, q0.x); ffma2(dot2[1], pb, q0.y);
                ffma2(dot2[2], pb, q1.x); ffma2(dot2[3], pb, q1.y);
                ffma2(dot2[4], pb, q2.x); ffma2(dot2[5], pb, q2.y);
                ffma2(dot2[6], pb, q3.x); ffma2(dot2[7], pb, q3.y);
            }
        }
    }

    float2 et = upk2(energy2);
    float energy = et.x + et.y;
    float2 nt = upk2(n22);
    float n2 = nt.x + nt.y;

    __syncthreads();

    // ---- energy max over block ----
    float wm = warp_max(energy);
    if (lane == 0) red_s[wid] = wm;
    __syncthreads();
    if (tid == 0) {
        float m = red_s[0];
        for (int w = 1; w < 22; w++) m = fmaxf(m, red_s[w]);
        s_emax = m;
    }
    __syncthreads();

    float denom = fmaxf(s_emax * (1.f / 256.f), EPSV);
    float en = (energy * (1.f / 256.f)) / denom;
    bool amb = en > GATE;

    float cw = warp_sum(amb ? 1.f : 0.f);
    if (lane == 0) red_s[wid] = cw;
    __syncthreads();
    if (tid == 0) {
        float m = 0.f;
        for (int w = 0; w < 22; w++) m += red_s[w];
        s_cnt = m;
    }
    __syncthreads();
    if (s_cnt <= 0.f) amb = (energy > 0.f);
    float am_f = amb ? 1.f : 0.f;

    // ---- logits -> softmax -> supp (registers) ----
    float d[KK];
#pragma unroll
    for (int j = 0; j < 8; j++) {
        float2 t = upk2(dot2[j]);
        d[2 * j] = t.x;
        d[2 * j + 1] = t.y;
    }
    float inv = 1.f / fmaxf(sqrtf(n2), 1e-12f);
    float mx = -1e30f;
#pragma unroll
    for (int k = 0; k < KK; k++) { d[k] = d[k] * inv * 8.f; mx = fmaxf(mx, d[k]); }
    float se = 0.f;
#pragma unroll
    for (int k = 0; k < KK; k++) { d[k] = __expf(d[k] - mx); se += d[k]; }
    float sc = am_f / se;   // supp[k] = d[k]*sc

    float* supp_s = smem_pool;   // reuse (lbn/tile done)
#pragma unroll
    for (int k = 0; k < KK; k++) supp_s[k * NPOS + p] = d[k] * sc;
    __syncthreads();

    // ---- per-k: colsum + exact top-88 presence (warp k owns column k) ----
    if (wid < KK) {
        float vals[22];
        float s = 0.f;
#pragma unroll
        for (int i = 0; i < 22; i++) {
            vals[i] = supp_s[wid * NPOS + lane + 32 * i];
            s += vals[i];
        }
        s = warp_sum(s);
        if (lane == 0) colsum_s[wid] = s;

        // binary search on nonneg float bit patterns for 88th largest
        unsigned V = 0u;
        for (int bit = 30; bit >= 0; --bit) {
            unsigned cand = V | (1u << bit);
            float cf = __uint_as_float(cand);
            int cnt = 0;
#pragma unroll
            for (int i = 0; i < 22; i++) cnt += (vals[i] >= cf) ? 1 : 0;
            cnt = __reduce_add_sync(0xffffffffu, cnt);
            if (cnt >= TOPK) V = cand;
        }
        float kth = __uint_as_float(V);
        int cgt = 0;
        float sgt = 0.f;
#pragma unroll
        for (int i = 0; i < 22; i++) {
            if (vals[i] > kth) { cgt++; sgt += vals[i]; }
        }
        cgt = __reduce_add_sync(0xffffffffu, cgt);
        sgt = warp_sum(sgt);
        if (lane == 0) {
            float pr = (sgt + kth * (float)(TOPK - cgt)) * (1.f / (float)TOPK);
            pres_out[n * (GG * KK) + g * KK + wid] = pr;
        }
    }
    __syncthreads();
    if (tid < KK) pinv_s[tid] = 1.f / fmaxf(colsum_s[tid], EPSV);
    __syncthreads();

    // ---- pw = supp / colsum -> global scratch ----
    float* gpw = g_pw + (size_t)(n * GG + g) * KK * NPOS;
#pragma unroll
    for (int k = 0; k < KK; k++) gpw[k * NPOS + p] = d[k] * sc * pinv_s[k];
}

// =====================================================================
// Kernel 2: tokens[k][c] = sum_p pw[p][k] * x[c][p].  CTA = (g, n),
// 128 threads, thread = channels (c, c+128).
// x staged through a padded smem tile per 32-position chunk (coalesced
// LDG, conflict-free LDS); pw resident in smem, warp-uniform broadcast
// LDS128 (R7 core). 80KB dynamic smem, 2 CTAs/SM.
// =====================================================================
#define PCH 32               // positions per chunk
#define NCHUNK 22            // 704/32
#define XS_STRIDE 36         // floats per channel row in x_s (8 float4 + pad)
#define XS_FLOATS (CC * XS_STRIDE)        // 9216 floats = 36864 B
#define TOK_SMEM ((XS_FLOATS + KK * NPOS) * 4)   // 36864 + 45056 = 81920 B

__global__ void __launch_bounds__(128) k_tokens(const float* __restrict__ x,
                                                float* __restrict__ out) {
    extern __shared__ __align__(16) float dsm[];
    float* x_s  = dsm;                 // [256][36]
    float* pw_s = dsm + XS_FLOATS;     // [16][704]

    const int g = blockIdx.x, n = blockIdx.y;
    const int tid = threadIdx.x;

    // load pw into smem once (coalesced; first loop barrier orders it)
    {
        const float4* src = (const float4*)(g_pw + (size_t)(n * GG + g) * KK * NPOS);
        float4* dst = (float4*)pw_s;
#pragma unroll
        for (int i = 0; i < 22; i++) dst[tid + 128 * i] = src[tid + 128 * i];
    }

    const float* xg = x + (size_t)n * CC * CH_STRIDE + (size_t)g * NPOS;
    const int c0 = tid;
    const int c1 = tid + 128;

    unsigned long long accA[KK], accB[KK];
#pragma unroll
    for (int k = 0; k < KK; k++) { accA[k] = 0ULL; accB[k] = 0ULL; }

    for (int ch = 0; ch < NCHUNK; ch++) {
        const int p0 = ch * PCH;
        __syncthreads();   // prior chunk x_s reads done (and pw_s ready on ch=0)
        // stage 256 channels x 32 positions, coalesced LDG -> padded smem
#pragma unroll
        for (int it = 0; it < 16; it++) {
            int f = tid + 128 * it;          // 0..2047
            int c = f >> 3, i = f & 7;
            float4 vv = __ldg((const float4*)(xg + (size_t)c * CH_STRIDE + p0) + i);
            *(float4*)(x_s + c * XS_STRIDE + i * 4) = vv;
        }
        __syncthreads();

        const int p4base = ch * (PCH / 4);
#pragma unroll
        for (int i = 0; i < 8; i++) {
            float4 xa = *(const float4*)(x_s + c0 * XS_STRIDE + i * 4);
            float4 xb = *(const float4*)(x_s + c1 * XS_STRIDE + i * 4);
            unsigned long long alo = pk2(xa.x, xa.y);
            unsigned long long ahi = pk2(xa.z, xa.w);
            unsigned long long blo = pk2(xb.x, xb.y);
            unsigned long long bhi = pk2(xb.z, xb.w);
            const float* pwrow = pw_s + 4 * (p4base + i);
#pragma unroll
            for (int k = 0; k < KK; k++) {
                ulonglong2 pv = *(const ulonglong2*)(pwrow + k * NPOS);  // broadcast
                ffma2(accA[k], alo, pv.x);
                ffma2(accA[k], ahi, pv.y);
                ffma2(accB[k], blo, pv.x);
                ffma2(accB[k], bhi, pv.y);
            }
        }
    }

    float resA[KK], resB[KK];
#pragma unroll
    for (int k = 0; k < KK; k++) {
        float2 ta = upk2(accA[k]);
        resA[k] = ta.x + ta.y;
        float2 tb = upk2(accB[k]);
        resB[k] = tb.x + tb.y;
    }
    float4* oa = (float4*)(out + (size_t)(n * CC + c0) * (GG * KK) + g * KK);
    oa[0] = make_float4(resA[0], resA[1], resA[2], resA[3]);
    oa[1] = make_float4(resA[4], resA[5], resA[6], resA[7]);
    oa[2] = make_float4(resA[8], resA[9], resA[10], resA[11]);
    oa[3] = make_float4(resA[12], resA[13], resA[14], resA[15]);
    float4* ob = (float4*)(out + (size_t)(n * CC + c1) * (GG * KK) + g * KK);
    ob[0] = make_float4(resB[0], resB[1], resB[2], resB[3]);
    ob[1] = make_float4(resB[4], resB[5], resB[6], resB[7]);
    ob[2] = make_float4(resB[8], resB[9], resB[10], resB[11]);
    ob[3] = make_float4(resB[12], resB[13], resB[14], resB[15]);
}

// =====================================================================
// Kernel 3: normalize presence per n (in place).
// =====================================================================
__global__ void k_presnorm(float* __restrict__ pres) {
    const int n = blockIdx.x;
    const int t = threadIdx.x;
    float v = pres[n * 64 + t];
    float s = warp_sum(v);
    __shared__ float sh[2];
    if ((t & 31) == 0) sh[t >> 5] = s;
    __syncthreads();
    float tot = sh[0] + sh[1];
    pres[n * 64 + t] = v / fmaxf(tot, EPSV);
}

extern "C" void kernel_launch(void* const* d_in, const int* in_sizes, int n_in,
                              void* d_out, int out_size) {
    const float* x = (const float*)d_in[0];
    const float* lb = (const float*)d_in[1];
    float* out = (float*)d_out;
    float* pres = out + (size_t)NN * CC * (GG * KK);   // tokens first, then pres

    static int smem_set = 0;
    if (!smem_set) {
        cudaFuncSetAttribute(k_tokens, cudaFuncAttributeMaxDynamicSharedMemorySize, TOK_SMEM);
        smem_set = 1;
    }

    dim3 grid(GG, NN);
    k_route<<<grid, NPOS>>>(x, lb, pres);
    k_tokens<<<grid, 128, TOK_SMEM>>>(x, out);
    k_presnorm<<<NN, 64>>>(pres);
}